// round 7
// baseline (speedup 1.0000x reference)
#include <cuda_runtime.h>
#include <cuda_fp16.h>
#include <cstdint>

#define T_DIM 4096
#define H_DIM 2048
#define F_DIM 7168

// ---------------- scratch (device globals; no runtime allocation) ------------
__device__ __align__(1024) __half g_xh  [(size_t)T_DIM * H_DIM];   // x  fp16 [T,H]
__device__ __align__(1024) __half g_w1h [(size_t)F_DIM * H_DIM];   // w1 fp16 [F,H]
__device__ __align__(1024) __half g_w3h [(size_t)F_DIM * H_DIM];   // w3 fp16 [F,H]
__device__ __align__(1024) __half g_w2h [(size_t)H_DIM * F_DIM];   // w2 fp16 [H,F]
__device__ __align__(1024) __half g_fused[(size_t)T_DIM * F_DIM];  // silu(g)*u fp16 [T,F]

// ---------------- helpers -----------------------------------------------------
__device__ __forceinline__ float silu_f(float v) { return v / (1.0f + __expf(-v)); }

__device__ __forceinline__ uint32_t smem_u32(const void* p) {
    uint32_t a;
    asm("{ .reg .u64 t; cvta.to.shared.u64 t, %1; cvt.u32.u64 %0, t; }" : "=r"(a) : "l"(p));
    return a;
}

#define SW128(o) ((o) ^ (((o) >> 3) & 0x70))

__device__ __forceinline__ void cp16(uint32_t dst, const void* src) {
    asm volatile("cp.async.cg.shared.global [%0], [%1], 16;\n" :: "r"(dst), "l"(src));
}

__device__ __forceinline__ void mma16816(float c[4], const uint32_t a[4], const uint32_t b[2]) {
    asm volatile(
        "mma.sync.aligned.m16n8k16.row.col.f32.f16.f16.f32 "
        "{%0,%1,%2,%3}, {%4,%5,%6,%7}, {%8,%9}, {%0,%1,%2,%3};\n"
        : "+f"(c[0]), "+f"(c[1]), "+f"(c[2]), "+f"(c[3])
        : "r"(a[0]), "r"(a[1]), "r"(a[2]), "r"(a[3]), "r"(b[0]), "r"(b[1]));
}

__device__ __forceinline__ void ldsm4(uint32_t* r, uint32_t addr) {
    asm volatile("ldmatrix.sync.aligned.m8n8.x4.shared.b16 {%0,%1,%2,%3}, [%4];"
                 : "=r"(r[0]), "=r"(r[1]), "=r"(r[2]), "=r"(r[3]) : "r"(addr));
}

// ---------------- conversion / dequant kernels --------------------------------
__global__ void cvt_x_kernel(const float4* __restrict__ in, __half2* __restrict__ out, int n4) {
    for (int i = blockIdx.x * blockDim.x + threadIdx.x; i < n4; i += gridDim.x * blockDim.x) {
        float4 v = in[i];
        out[2 * i]     = __floats2half2_rn(v.x, v.y);
        out[2 * i + 1] = __floats2half2_rn(v.z, v.w);
    }
}

__global__ void dequant_kernel(const float4* __restrict__ wq, const float* __restrict__ ws,
                               __half2* __restrict__ out, int N, int K) {
    int total4 = (N * K) >> 2;
    for (int i = blockIdx.x * blockDim.x + threadIdx.x; i < total4; i += gridDim.x * blockDim.x) {
        int e = i << 2;
        int n = e / K;
        int k = e - n * K;
        float s = ws[(n >> 7) * (K >> 7) + (k >> 7)];
        float4 v = wq[i];
        out[2 * i]     = __floats2half2_rn(v.x * s, v.y * s);
        out[2 * i + 1] = __floats2half2_rn(v.z * s, v.w * s);
    }
}

// ---------------- HMMA GEMM ---------------------------------------------------
// C[128,128] per CTA = A @ B^T, fp16 operands, fp32 accum.
// DUAL: two B operands (w1,w3); epilogue silu(g)*u -> f16 outH.
// else: single B (w2); epilogue f32 -> outF.
// BK=64 halfs (128B SW128 rows). 3-stage cp.async pipeline. 16 warps (4x4).
// Warp tile 32x32 (per B matrix). ldmatrix.x4 + fragment double buffering.

template <bool DUAL>
__global__ void __launch_bounds__(512, 1)
gemm_hmma(const __half* __restrict__ A, const __half* __restrict__ B0g,
          const __half* __restrict__ B1g, __half* __restrict__ outH,
          float* __restrict__ outF, int K, int Nglobal) {
    extern __shared__ __align__(1024) char smem[];
    const uint32_t sb = smem_u32(smem);
    const int tid = threadIdx.x, lane = tid & 31, warp = tid >> 5;
    const int wm = warp >> 2, wn = warp & 3;
    const int bm = blockIdx.x, bn = blockIdx.y;
    const int NK = K >> 6;
    const int STAGE = DUAL ? 49152 : 32768;

    const __half* Ag  = A   + (size_t)(bm * 128) * K;
    const __half* Bg0 = B0g + (size_t)(bn * 128) * K;
    const __half* Bg1 = DUAL ? (B1g + (size_t)(bn * 128) * K) : nullptr;

    // per-lane ldmatrix row/col components
    const int qr = lane >> 3, rin = lane & 7;
    const uint32_t swx    = (uint32_t)rin << 4;
    const uint32_t laneAr = (uint32_t)((qr & 1) * 1024 + rin * 128);
    const uint32_t kqA    = (uint32_t)((qr >> 1) << 4);
    const uint32_t laneBr = (uint32_t)((lane >> 4) * 1024 + rin * 128);
    const uint32_t kqB    = (uint32_t)(((lane >> 3) & 1) << 4);

    float acc0[2][4][4], acc1[2][4][4];
    #pragma unroll
    for (int mf = 0; mf < 2; mf++)
        #pragma unroll
        for (int nf = 0; nf < 4; nf++)
            #pragma unroll
            for (int i = 0; i < 4; i++) {
                acc0[mf][nf][i] = 0.f;
                if (DUAL) acc1[mf][nf][i] = 0.f;
            }

    auto load_chunk = [&](int c, int buf) {
        const uint32_t st = sb + (uint32_t)buf * STAGE;
        const int ko = c * 64;
        #pragma unroll
        for (int i = tid; i < 1024; i += 512) {
            int r = i >> 3, cc = i & 7;
            cp16(st + SW128(r * 128 + cc * 16), Ag + (size_t)r * K + ko + cc * 8);
        }
        #pragma unroll
        for (int i = tid; i < 1024; i += 512) {
            int r = i >> 3, cc = i & 7;
            cp16(st + 16384 + SW128(r * 128 + cc * 16), Bg0 + (size_t)r * K + ko + cc * 8);
        }
        if (DUAL) {
            #pragma unroll
            for (int i = tid; i < 1024; i += 512) {
                int r = i >> 3, cc = i & 7;
                cp16(st + 32768 + SW128(r * 128 + cc * 16), Bg1 + (size_t)r * K + ko + cc * 8);
            }
        }
        asm volatile("cp.async.commit_group;\n");
    };

    load_chunk(0, 0);
    load_chunk(1, 1);

    for (int kt = 0; kt < NK; kt++) {
        if (kt + 1 < NK) asm volatile("cp.async.wait_group 1;\n");
        else             asm volatile("cp.async.wait_group 0;\n");
        __syncthreads();

        const uint32_t st = sb + (uint32_t)(kt % 3) * STAGE;
        const uint32_t Abase  = st + wm * 4096 + laneAr;
        const uint32_t B0base = st + 16384 + wn * 4096 + laneBr;
        const uint32_t B1base = st + 32768 + wn * 4096 + laneBr;

        // fragment double buffers (A, B0); B1 loaded JIT covered by acc0 MMAs
        uint32_t aF[2][2][4], b0F[2][2][4];

        // prefetch ks=0 fragments immediately so the tensor pipe restarts early
        {
            const uint32_t ac = kqA ^ swx;
            const uint32_t bc = kqB ^ swx;
            ldsm4(aF[0][0], Abase + ac);
            ldsm4(aF[0][1], Abase + 2048 + ac);
            ldsm4(b0F[0][0], B0base + bc);
            ldsm4(b0F[0][1], B0base + 2048 + bc);
        }

        // next-chunk global loads have ~2 chunks of slack; issue after frag prefetch
        if (kt + 2 < NK) load_chunk(kt + 2, (kt + 2) % 3);

        #pragma unroll
        for (int ks = 0; ks < 4; ks++) {
            const int cur = ks & 1, nxt = cur ^ 1;

            uint32_t b1F[2][4];
            if (DUAL) {
                const uint32_t bc = ((uint32_t)(ks * 32) + kqB) ^ swx;
                ldsm4(b1F[0], B1base + bc);
                ldsm4(b1F[1], B1base + 2048 + bc);
            }
            if (ks < 3) {
                const uint32_t ac = ((uint32_t)((ks + 1) * 32) + kqA) ^ swx;
                const uint32_t bc = ((uint32_t)((ks + 1) * 32) + kqB) ^ swx;
                ldsm4(aF[nxt][0], Abase + ac);
                ldsm4(aF[nxt][1], Abase + 2048 + ac);
                ldsm4(b0F[nxt][0], B0base + bc);
                ldsm4(b0F[nxt][1], B0base + 2048 + bc);
            }

            #pragma unroll
            for (int mf = 0; mf < 2; mf++)
                #pragma unroll
                for (int nf = 0; nf < 4; nf++) {
                    const uint32_t bb[2] = { b0F[cur][nf >> 1][(nf & 1) * 2],
                                             b0F[cur][nf >> 1][(nf & 1) * 2 + 1] };
                    mma16816(acc0[mf][nf], aF[cur][mf], bb);
                }
            if (DUAL) {
                #pragma unroll
                for (int mf = 0; mf < 2; mf++)
                    #pragma unroll
                    for (int nf = 0; nf < 4; nf++) {
                        const uint32_t bc[2] = { b1F[nf >> 1][(nf & 1) * 2],
                                                 b1F[nf >> 1][(nf & 1) * 2 + 1] };
                        mma16816(acc1[mf][nf], aF[cur][mf], bc);
                    }
            }
        }
    }

    // epilogue
    const int g = lane >> 2, t = lane & 3;
    const int row0 = bm * 128 + wm * 32;
    const int col0 = bn * 128 + wn * 32;
    #pragma unroll
    for (int mf = 0; mf < 2; mf++) {
        #pragma unroll
        for (int nf = 0; nf < 4; nf++) {
            const int r = row0 + mf * 16 + g;
            const int c = col0 + nf * 8 + 2 * t;
            if (DUAL) {
                float s0 = silu_f(acc0[mf][nf][0]) * acc1[mf][nf][0];
                float s1 = silu_f(acc0[mf][nf][1]) * acc1[mf][nf][1];
                float s2 = silu_f(acc0[mf][nf][2]) * acc1[mf][nf][2];
                float s3 = silu_f(acc0[mf][nf][3]) * acc1[mf][nf][3];
                *(__half2*)(outH + (size_t)r * Nglobal + c)       = __floats2half2_rn(s0, s1);
                *(__half2*)(outH + (size_t)(r + 8) * Nglobal + c) = __floats2half2_rn(s2, s3);
            } else {
                *(float2*)(outF + (size_t)r * Nglobal + c) =
                    make_float2(acc0[mf][nf][0], acc0[mf][nf][1]);
                *(float2*)(outF + (size_t)(r + 8) * Nglobal + c) =
                    make_float2(acc0[mf][nf][2], acc0[mf][nf][3]);
            }
        }
    }
}

// ---------------- launch ------------------------------------------------------
extern "C" void kernel_launch(void* const* d_in, const int* in_sizes, int n_in,
                              void* d_out, int out_size) {
    const float* x   = (const float*)d_in[0];  // [T,H]
    const float* w1q = (const float*)d_in[1];  // [F,H]
    const float* w1s = (const float*)d_in[2];
    const float* w3q = (const float*)d_in[3];  // [F,H]
    const float* w3s = (const float*)d_in[4];
    const float* w2q = (const float*)d_in[5];  // [H,F]
    const float* w2s = (const float*)d_in[6];

    __half *xh, *w1h, *w3h, *w2h, *fused;
    cudaGetSymbolAddress((void**)&xh,    g_xh);
    cudaGetSymbolAddress((void**)&w1h,   g_w1h);
    cudaGetSymbolAddress((void**)&w3h,   g_w3h);
    cudaGetSymbolAddress((void**)&w2h,   g_w2h);
    cudaGetSymbolAddress((void**)&fused, g_fused);

    const int SMEM_DUAL = 3 * 49152;  // 147456
    const int SMEM_SGL  = 3 * 32768;  //  98304
    cudaFuncSetAttribute((const void*)gemm_hmma<true>,
                         cudaFuncAttributeMaxDynamicSharedMemorySize, SMEM_DUAL);
    cudaFuncSetAttribute((const void*)gemm_hmma<false>,
                         cudaFuncAttributeMaxDynamicSharedMemorySize, SMEM_SGL);

    // 1) x -> fp16
    cvt_x_kernel<<<2048, 256>>>((const float4*)x, (__half2*)xh, (T_DIM * H_DIM) >> 2);
    // 2) dequant weights -> fp16
    dequant_kernel<<<4096, 256>>>((const float4*)w1q, w1s, (__half2*)w1h, F_DIM, H_DIM);
    dequant_kernel<<<4096, 256>>>((const float4*)w3q, w3s, (__half2*)w3h, F_DIM, H_DIM);
    dequant_kernel<<<4096, 256>>>((const float4*)w2q, w2s, (__half2*)w2h, H_DIM, F_DIM);
    // 3) fused dual GEMM: fused = silu(x@w1^T) * (x@w3^T)   [T,F] f16
    {
        dim3 grid(T_DIM / 128, F_DIM / 128);
        gemm_hmma<true><<<grid, 512, SMEM_DUAL>>>(xh, w1h, w3h, fused, nullptr,
                                                  H_DIM, F_DIM);
    }
    // 4) out = fused @ w2^T   [T,H] f32
    {
        dim3 grid(T_DIM / 128, H_DIM / 128);
        gemm_hmma<false><<<grid, 512, SMEM_SGL>>>(fused, w2h, nullptr, nullptr,
                                                  (float*)d_out, F_DIM, H_DIM);
    }
}

// round 8
// speedup vs baseline: 1.0680x; 1.0680x over previous
#include <cuda_runtime.h>
#include <cuda_fp16.h>
#include <cstdint>

#define T_DIM 4096
#define H_DIM 2048
#define F_DIM 7168

// ---------------- scratch (device globals; no runtime allocation) ------------
__device__ __align__(1024) __half g_xh  [(size_t)T_DIM * H_DIM];   // x  fp16 [T,H]
__device__ __align__(1024) __half g_w1h [(size_t)F_DIM * H_DIM];   // w1 fp16 [F,H]
__device__ __align__(1024) __half g_w3h [(size_t)F_DIM * H_DIM];   // w3 fp16 [F,H]
__device__ __align__(1024) __half g_w2h [(size_t)H_DIM * F_DIM];   // w2 fp16 [H,F]
__device__ __align__(1024) __half g_fused[(size_t)T_DIM * F_DIM];  // silu(g)*u fp16 [T,F]

// ---------------- helpers -----------------------------------------------------
__device__ __forceinline__ float silu_f(float v) { return v / (1.0f + __expf(-v)); }

__device__ __forceinline__ uint32_t smem_u32(const void* p) {
    uint32_t a;
    asm("{ .reg .u64 t; cvta.to.shared.u64 t, %1; cvt.u32.u64 %0, t; }" : "=r"(a) : "l"(p));
    return a;
}

#define SW128(o) ((o) ^ (((o) >> 3) & 0x70))

__device__ __forceinline__ void cp16(uint32_t dst, const void* src) {
    asm volatile("cp.async.cg.shared.global [%0], [%1], 16;\n" :: "r"(dst), "l"(src));
}

__device__ __forceinline__ void mma16816(float c[4], const uint32_t a[4], const uint32_t b[2]) {
    asm volatile(
        "mma.sync.aligned.m16n8k16.row.col.f32.f16.f16.f32 "
        "{%0,%1,%2,%3}, {%4,%5,%6,%7}, {%8,%9}, {%0,%1,%2,%3};\n"
        : "+f"(c[0]), "+f"(c[1]), "+f"(c[2]), "+f"(c[3])
        : "r"(a[0]), "r"(a[1]), "r"(a[2]), "r"(a[3]), "r"(b[0]), "r"(b[1]));
}

__device__ __forceinline__ void ldsm4(uint32_t* r, uint32_t addr) {
    asm volatile("ldmatrix.sync.aligned.m8n8.x4.shared.b16 {%0,%1,%2,%3}, [%4];"
                 : "=r"(r[0]), "=r"(r[1]), "=r"(r[2]), "=r"(r[3]) : "r"(addr));
}

// ---------------- conversion / dequant kernels --------------------------------
__global__ void cvt_x_kernel(const float4* __restrict__ in, __half2* __restrict__ out, int n4) {
    for (int i = blockIdx.x * blockDim.x + threadIdx.x; i < n4; i += gridDim.x * blockDim.x) {
        float4 v = in[i];
        out[2 * i]     = __floats2half2_rn(v.x, v.y);
        out[2 * i + 1] = __floats2half2_rn(v.z, v.w);
    }
}

__global__ void dequant_kernel(const float4* __restrict__ wq, const float* __restrict__ ws,
                               __half2* __restrict__ out, int N, int K) {
    int total4 = (N * K) >> 2;
    for (int i = blockIdx.x * blockDim.x + threadIdx.x; i < total4; i += gridDim.x * blockDim.x) {
        int e = i << 2;
        int n = e / K;
        int k = e - n * K;
        float s = ws[(n >> 7) * (K >> 7) + (k >> 7)];
        float4 v = wq[i];
        out[2 * i]     = __floats2half2_rn(v.x * s, v.y * s);
        out[2 * i + 1] = __floats2half2_rn(v.z * s, v.w * s);
    }
}

// ---------------- GEMM1: dual-B HMMA ------------------------------------------
// C[128,128] per CTA; two B operands (w1,w3); epilogue silu(g)*u -> f16.
// BK=64, 3-stage cp.async, 16 warps (4x4), warp tile 32x32 per B.
__global__ void __launch_bounds__(512, 1)
gemm_dualB(const __half* __restrict__ A, const __half* __restrict__ B0g,
           const __half* __restrict__ B1g, __half* __restrict__ outH,
           int K, int Nglobal) {
    extern __shared__ __align__(1024) char smem[];
    const uint32_t sb = smem_u32(smem);
    const int tid = threadIdx.x, lane = tid & 31, warp = tid >> 5;
    const int wm = warp >> 2, wn = warp & 3;
    const int bm = blockIdx.x, bn = blockIdx.y;
    const int NK = K >> 6;
    const int STAGE = 49152;

    const __half* Ag  = A   + (size_t)(bm * 128) * K;
    const __half* Bg0 = B0g + (size_t)(bn * 128) * K;
    const __half* Bg1 = B1g + (size_t)(bn * 128) * K;

    const int qr = lane >> 3, rin = lane & 7;
    const uint32_t swx    = (uint32_t)rin << 4;
    const uint32_t laneAr = (uint32_t)((qr & 1) * 1024 + rin * 128);
    const uint32_t kqA    = (uint32_t)((qr >> 1) << 4);
    const uint32_t laneBr = (uint32_t)((lane >> 4) * 1024 + rin * 128);
    const uint32_t kqB    = (uint32_t)(((lane >> 3) & 1) << 4);

    float acc0[2][4][4], acc1[2][4][4];
    #pragma unroll
    for (int mf = 0; mf < 2; mf++)
        #pragma unroll
        for (int nf = 0; nf < 4; nf++)
            #pragma unroll
            for (int i = 0; i < 4; i++) { acc0[mf][nf][i] = 0.f; acc1[mf][nf][i] = 0.f; }

    auto load_chunk = [&](int c, int buf) {
        const uint32_t st = sb + (uint32_t)buf * STAGE;
        const int ko = c * 64;
        #pragma unroll
        for (int i = tid; i < 1024; i += 512) {
            int r = i >> 3, cc = i & 7;
            cp16(st + SW128(r * 128 + cc * 16), Ag + (size_t)r * K + ko + cc * 8);
        }
        #pragma unroll
        for (int i = tid; i < 1024; i += 512) {
            int r = i >> 3, cc = i & 7;
            cp16(st + 16384 + SW128(r * 128 + cc * 16), Bg0 + (size_t)r * K + ko + cc * 8);
        }
        #pragma unroll
        for (int i = tid; i < 1024; i += 512) {
            int r = i >> 3, cc = i & 7;
            cp16(st + 32768 + SW128(r * 128 + cc * 16), Bg1 + (size_t)r * K + ko + cc * 8);
        }
        asm volatile("cp.async.commit_group;\n");
    };

    load_chunk(0, 0);
    load_chunk(1, 1);

    for (int kt = 0; kt < NK; kt++) {
        if (kt + 1 < NK) asm volatile("cp.async.wait_group 1;\n");
        else             asm volatile("cp.async.wait_group 0;\n");
        __syncthreads();

        const uint32_t st = sb + (uint32_t)(kt % 3) * STAGE;
        const uint32_t Abase  = st + wm * 4096 + laneAr;
        const uint32_t B0base = st + 16384 + wn * 4096 + laneBr;
        const uint32_t B1base = st + 32768 + wn * 4096 + laneBr;

        uint32_t aF[2][2][4], b0F[2][2][4];
        {
            const uint32_t ac = kqA ^ swx, bc = kqB ^ swx;
            ldsm4(aF[0][0], Abase + ac);
            ldsm4(aF[0][1], Abase + 2048 + ac);
            ldsm4(b0F[0][0], B0base + bc);
            ldsm4(b0F[0][1], B0base + 2048 + bc);
        }
        if (kt + 2 < NK) load_chunk(kt + 2, (kt + 2) % 3);

        #pragma unroll
        for (int ks = 0; ks < 4; ks++) {
            const int cur = ks & 1, nxt = cur ^ 1;
            uint32_t b1F[2][4];
            {
                const uint32_t bc = ((uint32_t)(ks * 32) + kqB) ^ swx;
                ldsm4(b1F[0], B1base + bc);
                ldsm4(b1F[1], B1base + 2048 + bc);
            }
            if (ks < 3) {
                const uint32_t ac = ((uint32_t)((ks + 1) * 32) + kqA) ^ swx;
                const uint32_t bc = ((uint32_t)((ks + 1) * 32) + kqB) ^ swx;
                ldsm4(aF[nxt][0], Abase + ac);
                ldsm4(aF[nxt][1], Abase + 2048 + ac);
                ldsm4(b0F[nxt][0], B0base + bc);
                ldsm4(b0F[nxt][1], B0base + 2048 + bc);
            }
            #pragma unroll
            for (int mf = 0; mf < 2; mf++)
                #pragma unroll
                for (int nf = 0; nf < 4; nf++) {
                    const uint32_t bb[2] = { b0F[cur][nf >> 1][(nf & 1) * 2],
                                             b0F[cur][nf >> 1][(nf & 1) * 2 + 1] };
                    mma16816(acc0[mf][nf], aF[cur][mf], bb);
                }
            #pragma unroll
            for (int mf = 0; mf < 2; mf++)
                #pragma unroll
                for (int nf = 0; nf < 4; nf++) {
                    const uint32_t bc[2] = { b1F[nf >> 1][(nf & 1) * 2],
                                             b1F[nf >> 1][(nf & 1) * 2 + 1] };
                    mma16816(acc1[mf][nf], aF[cur][mf], bc);
                }
        }
    }

    const int g = lane >> 2, t = lane & 3;
    const int row0 = bm * 128 + wm * 32;
    const int col0 = bn * 128 + wn * 32;
    #pragma unroll
    for (int mf = 0; mf < 2; mf++) {
        #pragma unroll
        for (int nf = 0; nf < 4; nf++) {
            const int r = row0 + mf * 16 + g;
            const int c = col0 + nf * 8 + 2 * t;
            float s0 = silu_f(acc0[mf][nf][0]) * acc1[mf][nf][0];
            float s1 = silu_f(acc0[mf][nf][1]) * acc1[mf][nf][1];
            float s2 = silu_f(acc0[mf][nf][2]) * acc1[mf][nf][2];
            float s3 = silu_f(acc0[mf][nf][3]) * acc1[mf][nf][3];
            *(__half2*)(outH + (size_t)r * Nglobal + c)       = __floats2half2_rn(s0, s1);
            *(__half2*)(outH + (size_t)(r + 8) * Nglobal + c) = __floats2half2_rn(s2, s3);
        }
    }
}

// ---------------- GEMM2: dual-A HMMA ------------------------------------------
// C[256,128] per CTA as two 128-row halves sharing one B tile (w2).
// Same 192 B/MMA smem ratio as GEMM1 -> HMMA-bound instead of crossbar-bound.
__global__ void __launch_bounds__(512, 1)
gemm_dualA(const __half* __restrict__ A, const __half* __restrict__ Bg,
           float* __restrict__ outF, int K, int Nglobal) {
    extern __shared__ __align__(1024) char smem[];
    const uint32_t sb = smem_u32(smem);
    const int tid = threadIdx.x, lane = tid & 31, warp = tid >> 5;
    const int wm = warp >> 2, wn = warp & 3;
    const int bm = blockIdx.x, bn = blockIdx.y;
    const int NK = K >> 6;
    const int STAGE = 49152;

    const __half* Ag0 = A  + (size_t)(bm * 256) * K;
    const __half* Ag1 = Ag0 + (size_t)128 * K;
    const __half* Bg0 = Bg + (size_t)(bn * 128) * K;

    const int qr = lane >> 3, rin = lane & 7;
    const uint32_t swx    = (uint32_t)rin << 4;
    const uint32_t laneAr = (uint32_t)((qr & 1) * 1024 + rin * 128);
    const uint32_t kqA    = (uint32_t)((qr >> 1) << 4);
    const uint32_t laneBr = (uint32_t)((lane >> 4) * 1024 + rin * 128);
    const uint32_t kqB    = (uint32_t)(((lane >> 3) & 1) << 4);

    float acc0[2][4][4], acc1[2][4][4];
    #pragma unroll
    for (int mf = 0; mf < 2; mf++)
        #pragma unroll
        for (int nf = 0; nf < 4; nf++)
            #pragma unroll
            for (int i = 0; i < 4; i++) { acc0[mf][nf][i] = 0.f; acc1[mf][nf][i] = 0.f; }

    auto load_chunk = [&](int c, int buf) {
        const uint32_t st = sb + (uint32_t)buf * STAGE;
        const int ko = c * 64;
        #pragma unroll
        for (int i = tid; i < 1024; i += 512) {
            int r = i >> 3, cc = i & 7;
            cp16(st + SW128(r * 128 + cc * 16), Ag0 + (size_t)r * K + ko + cc * 8);
        }
        #pragma unroll
        for (int i = tid; i < 1024; i += 512) {
            int r = i >> 3, cc = i & 7;
            cp16(st + 16384 + SW128(r * 128 + cc * 16), Ag1 + (size_t)r * K + ko + cc * 8);
        }
        #pragma unroll
        for (int i = tid; i < 1024; i += 512) {
            int r = i >> 3, cc = i & 7;
            cp16(st + 32768 + SW128(r * 128 + cc * 16), Bg0 + (size_t)r * K + ko + cc * 8);
        }
        asm volatile("cp.async.commit_group;\n");
    };

    load_chunk(0, 0);
    load_chunk(1, 1);

    for (int kt = 0; kt < NK; kt++) {
        if (kt + 1 < NK) asm volatile("cp.async.wait_group 1;\n");
        else             asm volatile("cp.async.wait_group 0;\n");
        __syncthreads();

        const uint32_t st = sb + (uint32_t)(kt % 3) * STAGE;
        const uint32_t A0base = st + wm * 4096 + laneAr;
        const uint32_t A1base = st + 16384 + wm * 4096 + laneAr;
        const uint32_t Bbase  = st + 32768 + wn * 4096 + laneBr;

        uint32_t a0F[2][2][4], bF[2][2][4];
        {
            const uint32_t ac = kqA ^ swx, bc = kqB ^ swx;
            ldsm4(a0F[0][0], A0base + ac);
            ldsm4(a0F[0][1], A0base + 2048 + ac);
            ldsm4(bF[0][0], Bbase + bc);
            ldsm4(bF[0][1], Bbase + 2048 + bc);
        }
        if (kt + 2 < NK) load_chunk(kt + 2, (kt + 2) % 3);

        #pragma unroll
        for (int ks = 0; ks < 4; ks++) {
            const int cur = ks & 1, nxt = cur ^ 1;
            uint32_t a1F[2][4];
            {
                const uint32_t ac = ((uint32_t)(ks * 32) + kqA) ^ swx;
                ldsm4(a1F[0], A1base + ac);
                ldsm4(a1F[1], A1base + 2048 + ac);
            }
            if (ks < 3) {
                const uint32_t ac = ((uint32_t)((ks + 1) * 32) + kqA) ^ swx;
                const uint32_t bc = ((uint32_t)((ks + 1) * 32) + kqB) ^ swx;
                ldsm4(a0F[nxt][0], A0base + ac);
                ldsm4(a0F[nxt][1], A0base + 2048 + ac);
                ldsm4(bF[nxt][0], Bbase + bc);
                ldsm4(bF[nxt][1], Bbase + 2048 + bc);
            }
            #pragma unroll
            for (int mf = 0; mf < 2; mf++)
                #pragma unroll
                for (int nf = 0; nf < 4; nf++) {
                    const uint32_t bb[2] = { bF[cur][nf >> 1][(nf & 1) * 2],
                                             bF[cur][nf >> 1][(nf & 1) * 2 + 1] };
                    mma16816(acc0[mf][nf], a0F[cur][mf], bb);
                }
            #pragma unroll
            for (int mf = 0; mf < 2; mf++)
                #pragma unroll
                for (int nf = 0; nf < 4; nf++) {
                    const uint32_t bb[2] = { bF[cur][nf >> 1][(nf & 1) * 2],
                                             bF[cur][nf >> 1][(nf & 1) * 2 + 1] };
                    mma16816(acc1[mf][nf], a1F[mf], bb);
                }
        }
    }

    const int g = lane >> 2, t = lane & 3;
    const int row0 = bm * 256 + wm * 32;
    const int col0 = bn * 128 + wn * 32;
    #pragma unroll
    for (int mf = 0; mf < 2; mf++) {
        #pragma unroll
        for (int nf = 0; nf < 4; nf++) {
            const int r = row0 + mf * 16 + g;
            const int c = col0 + nf * 8 + 2 * t;
            *(float2*)(outF + (size_t)r * Nglobal + c) =
                make_float2(acc0[mf][nf][0], acc0[mf][nf][1]);
            *(float2*)(outF + (size_t)(r + 8) * Nglobal + c) =
                make_float2(acc0[mf][nf][2], acc0[mf][nf][3]);
            *(float2*)(outF + (size_t)(r + 128) * Nglobal + c) =
                make_float2(acc1[mf][nf][0], acc1[mf][nf][1]);
            *(float2*)(outF + (size_t)(r + 136) * Nglobal + c) =
                make_float2(acc1[mf][nf][2], acc1[mf][nf][3]);
        }
    }
}

// ---------------- launch ------------------------------------------------------
extern "C" void kernel_launch(void* const* d_in, const int* in_sizes, int n_in,
                              void* d_out, int out_size) {
    const float* x   = (const float*)d_in[0];  // [T,H]
    const float* w1q = (const float*)d_in[1];  // [F,H]
    const float* w1s = (const float*)d_in[2];
    const float* w3q = (const float*)d_in[3];  // [F,H]
    const float* w3s = (const float*)d_in[4];
    const float* w2q = (const float*)d_in[5];  // [H,F]
    const float* w2s = (const float*)d_in[6];

    __half *xh, *w1h, *w3h, *w2h, *fused;
    cudaGetSymbolAddress((void**)&xh,    g_xh);
    cudaGetSymbolAddress((void**)&w1h,   g_w1h);
    cudaGetSymbolAddress((void**)&w3h,   g_w3h);
    cudaGetSymbolAddress((void**)&w2h,   g_w2h);
    cudaGetSymbolAddress((void**)&fused, g_fused);

    const int SMEM = 3 * 49152;  // 147456
    cudaFuncSetAttribute((const void*)gemm_dualB,
                         cudaFuncAttributeMaxDynamicSharedMemorySize, SMEM);
    cudaFuncSetAttribute((const void*)gemm_dualA,
                         cudaFuncAttributeMaxDynamicSharedMemorySize, SMEM);

    // 1) x -> fp16
    cvt_x_kernel<<<2048, 256>>>((const float4*)x, (__half2*)xh, (T_DIM * H_DIM) >> 2);
    // 2) dequant weights -> fp16
    dequant_kernel<<<4096, 256>>>((const float4*)w1q, w1s, (__half2*)w1h, F_DIM, H_DIM);
    dequant_kernel<<<4096, 256>>>((const float4*)w3q, w3s, (__half2*)w3h, F_DIM, H_DIM);
    dequant_kernel<<<4096, 256>>>((const float4*)w2q, w2s, (__half2*)w2h, H_DIM, F_DIM);
    // 3) fused dual-B GEMM: fused = silu(x@w1^T) * (x@w3^T)   [T,F] f16
    {
        dim3 grid(T_DIM / 128, F_DIM / 128);
        gemm_dualB<<<grid, 512, SMEM>>>(xh, w1h, w3h, fused, H_DIM, F_DIM);
    }
    // 4) out = fused @ w2^T   [T,H] f32  (dual-A: 256-row CTA tiles share B)
    {
        dim3 grid(T_DIM / 256, H_DIM / 128);
        gemm_dualA<<<grid, 512, SMEM>>>(fused, w2h, (float*)d_out, F_DIM, H_DIM);
    }
}